// round 8
// baseline (speedup 1.0000x reference)
#include <cuda_runtime.h>
#include <cuda_bf16.h>

#define Dm 1024
#define Tm 2048
#define Lm 4

typedef unsigned long long u64;

// ---------------- device scratch (allocation-free rule) ---------------------
__device__ __align__(16) float g_seq[2][Tm * Dm];            // ping-pong seq
__device__ __align__(16) float g_zx[(size_t)Tm * 4 * Dm];    // x-part + bias
__device__ __align__(16) float g_h[2][Dm];                   // h double buffer
__device__ unsigned g_bar_count;
__device__ unsigned g_bar_gen;

// ---------------- f32x2 helpers (sm_103a packed fp32) -----------------------
__device__ __forceinline__ u64 ffma2(u64 a, u64 b, u64 c) {
    u64 d;
    asm("fma.rn.f32x2 %0, %1, %2, %3;" : "=l"(d) : "l"(a), "l"(b), "l"(c));
    return d;
}
__device__ __forceinline__ u64 pack2(float x, float y) {
    u64 r;
    asm("mov.b64 %0, {%1, %2};" : "=l"(r)
        : "r"(__float_as_uint(x)), "r"(__float_as_uint(y)));
    return r;
}
__device__ __forceinline__ float hsum2(u64 v) {
    unsigned lo, hi;
    asm("mov.b64 {%0, %1}, %2;" : "=r"(lo), "=r"(hi) : "l"(v));
    return __uint_as_float(lo) + __uint_as_float(hi);
}

// ---------------- software grid barrier --------------------------------------
__device__ __forceinline__ void gridbar(unsigned nctas) {
    __syncthreads();
    if (threadIdx.x == 0) {
        unsigned old = *((volatile unsigned*)&g_bar_gen);
        __threadfence();  // publish this CTA's writes before arrival
        if (atomicAdd(&g_bar_count, 1u) == nctas - 1u) {
            *((volatile unsigned*)&g_bar_count) = 0u;
            __threadfence();
            *((volatile unsigned*)&g_bar_gen) = old + 1u;
        } else {
            while (*((volatile unsigned*)&g_bar_gen) == old) {}
        }
        __threadfence();  // acquire
    }
    __syncthreads();
}

// ---------------- kernel 1: persistent Re bias-add ---------------------------
__global__ void bias_kernel(const float* __restrict__ x, const float* __restrict__ rn,
                            const float* __restrict__ w, const float* __restrict__ b) {
    int i = blockIdx.x * 256 + threadIdx.x;
    int j = i & (Dm - 1);
    g_seq[0][i] = x[i] + rn[0] * w[j] + b[j];
}

// ---------------- kernel 2: Zx = seq_in @ Wx + bias (f32x2 GEMM) -------------
// C tile 128(m) x 64(n), BK = 16, 256 threads, 8x4 per thread.
__global__ __launch_bounds__(256, 2) void gemm_zx(
    const float* __restrict__ Wf1, const float* __restrict__ Wf2,
    const float* __restrict__ Wta, const float* __restrict__ Wtb,
    const float* __restrict__ bf1, const float* __restrict__ bf2,
    const float* __restrict__ bta, const float* __restrict__ btb,
    int layer)
{
    __shared__ u64   As2[8][128];      // [k-pair][m]
    __shared__ float Bsf[8][64][2];    // [k-pair][n][k parity]

    const int tid = threadIdx.x;
    const int tx = tid & 15;           // n within tile (x16)
    const int ty = tid >> 4;           // m within tile (x16)
    const int m0 = blockIdx.y * 128;
    const int n0 = blockIdx.x * 64;    // global col in [0,4096)
    const int blk = n0 >> 10;          // which weight block
    const int j0  = n0 & (Dm - 1);

    const float* Wb = (blk == 0) ? Wf1 : ((blk == 1) ? Wf2 : ((blk == 2) ? Wta : Wtb));
    const float* bb = (blk == 0) ? bf1 : ((blk == 1) ? bf2 : ((blk == 2) ? bta : btb));
    const float* Bp = Wb + (size_t)layer * 2 * Dm * Dm + j0;   // x rows 0..D-1
    const float* A  = g_seq[layer & 1];

    u64 acc[8][4];
#pragma unroll
    for (int i = 0; i < 8; i++)
#pragma unroll
        for (int j = 0; j < 4; j++) acc[i][j] = 0ull;

    for (int k0 = 0; k0 < Dm; k0 += 16) {
        // A tile: 128 rows x 16 k  (512 float4, 2 per thread)
#pragma unroll
        for (int it = 0; it < 2; it++) {
            int i   = tid + it * 256;
            int row = i >> 2;
            int f4  = i & 3;
            float4 v = *(const float4*)(A + (size_t)(m0 + row) * Dm + k0 + f4 * 4);
            As2[f4 * 2 + 0][row] = pack2(v.x, v.y);
            As2[f4 * 2 + 1][row] = pack2(v.z, v.w);
        }
        // B tile: 16 k-rows x 64 cols (256 float4, 1 per thread)
        {
            int kr = tid >> 4;         // 0..15
            int j4 = tid & 15;         // 0..15
            float4 v = *(const float4*)(Bp + (size_t)(k0 + kr) * Dm + j4 * 4);
            Bsf[kr >> 1][j4 * 4 + 0][kr & 1] = v.x;
            Bsf[kr >> 1][j4 * 4 + 1][kr & 1] = v.y;
            Bsf[kr >> 1][j4 * 4 + 2][kr & 1] = v.z;
            Bsf[kr >> 1][j4 * 4 + 3][kr & 1] = v.w;
        }
        __syncthreads();
#pragma unroll
        for (int kk = 0; kk < 8; kk++) {
            u64 a2[8], b2[4];
#pragma unroll
            for (int ii = 0; ii < 8; ii++) a2[ii] = As2[kk][ii * 16 + ty];
#pragma unroll
            for (int jj = 0; jj < 4; jj++) b2[jj] = *(const u64*)&Bsf[kk][jj * 16 + tx][0];
#pragma unroll
            for (int ii = 0; ii < 8; ii++)
#pragma unroll
                for (int jj = 0; jj < 4; jj++)
                    acc[ii][jj] = ffma2(a2[ii], b2[jj], acc[ii][jj]);
        }
        __syncthreads();
    }

    float bias[4];
#pragma unroll
    for (int jj = 0; jj < 4; jj++) bias[jj] = bb[(size_t)layer * Dm + j0 + jj * 16 + tx];
#pragma unroll
    for (int ii = 0; ii < 8; ii++) {
        size_t row = (size_t)(m0 + ii * 16 + ty);
#pragma unroll
        for (int jj = 0; jj < 4; jj++)
            g_zx[row * 4096 + n0 + jj * 16 + tx] = hsum2(acc[ii][jj]) + bias[jj];
    }
}

// ---------------- kernel 3: sequential scan ----------------------------------
// 128 CTAs x 256 threads, persistent, grid-barrier per step.
// CTA b owns dims J = 8b .. 8b+7. Warp w handles dim J+w.
// Lane = blk*8 + chunk: blk picks the weight matrix (f1/f2/ta/tb),
// chunk picks k-range [chunk*128, chunk*128+128). Wh rows 1024..2047.
__global__ __launch_bounds__(256, 1) void scan_kernel(
    const float* __restrict__ Wf1, const float* __restrict__ Wf2,
    const float* __restrict__ Wta, const float* __restrict__ Wtb,
    const float* __restrict__ dt_ptr, int layer)
{
    __shared__ __align__(16) float sh[Dm];   // h staged, chunk-interleaved

    const int tid  = threadIdx.x;
    const int lane = tid & 31;
    const int w    = tid >> 5;               // warp -> dim
    const int blk  = lane >> 3;              // 0..3
    const int ch   = lane & 7;               // k chunk
    const int dim  = blockIdx.x * 8 + w;
    const float dt = dt_ptr[0];

    const float* Wsel = (blk == 0) ? Wf1 : ((blk == 1) ? Wf2 : ((blk == 2) ? Wta : Wtb));
    const float* Wp = Wsel + (size_t)layer * 2 * Dm * Dm
                    + (size_t)(Dm + ch * 128) * Dm + dim;

    // weights into registers: 64 f32x2 pairs = this lane's 128 k-values
    u64 wreg[64];
#pragma unroll
    for (int i = 0; i < 64; i++)
        wreg[i] = pack2(Wp[(size_t)(2 * i) * Dm], Wp[(size_t)(2 * i + 1) * Dm]);

    float* __restrict__ outseq = g_seq[(layer + 1) & 1];
    const bool zlane = (ch == 0);
    float zx_cur = zlane ? __ldg(&g_zx[(size_t)blk * Dm + dim]) : 0.0f;

    for (int t = 0; t < Tm; ++t) {
        // stage h_t into smem: sh word (f*32 + c*4 + j) = h[c*128 + f*4 + j]
        {
            int c = tid & 7, f = tid >> 3;   // f in 0..31
            float4 v;
            if (t == 0) { v.x = v.y = v.z = v.w = 0.0f; }
            else        { v = *(const float4*)&g_h[t & 1][c * 128 + f * 4]; }
            *(float4*)&sh[f * 32 + c * 4] = v;
        }
        __syncthreads();

        // prefetch Zx for next step (hidden behind compute + barrier)
        float zx_next = (zlane && t + 1 < Tm)
            ? __ldg(&g_zx[(size_t)(t + 1) * 4096 + blk * Dm + dim]) : 0.0f;

        // partial dot: 128 k-values via 64 packed FMAs (conflict-free LDS)
        u64 acc = 0ull;
        const float4* sh4 = (const float4*)sh;
#pragma unroll
        for (int f = 0; f < 32; f++) {
            float4 hv = sh4[f * 8 + ch];
            acc = ffma2(pack2(hv.x, hv.y), wreg[2 * f + 0], acc);
            acc = ffma2(pack2(hv.z, hv.w), wreg[2 * f + 1], acc);
        }
        float s = hsum2(acc);
        // reduce over 8 chunks within each block group
        s += __shfl_xor_sync(0xffffffffu, s, 1);
        s += __shfl_xor_sync(0xffffffffu, s, 2);
        s += __shfl_xor_sync(0xffffffffu, s, 4);
        if (zlane) s += zx_cur;              // lanes 0,8,16,24 hold z per block

        float z1 = __shfl_sync(0xffffffffu, s, 0);
        float z2 = __shfl_sync(0xffffffffu, s, 8);
        float za = __shfl_sync(0xffffffffu, s, 16);
        float zb = __shfl_sync(0xffffffffu, s, 24);

        float f1 = tanhf(z1);
        float f2 = tanhf(z2);
        float g  = 1.0f / (1.0f + expf(za * dt - zb));   // sigmoid(-za*dt+zb)
        float hn = g * f1 + (1.0f - g) * f2;

        if (lane == 0) {
            g_h[(t + 1) & 1][dim] = hn;
            outseq[(size_t)t * Dm + dim] = hn;
        }
        zx_cur = zx_next;
        if (t + 1 < Tm) gridbar(gridDim.x);
    }
}

// ---------------- kernel 4: emit final h -------------------------------------
__global__ void copy_out_kernel(float* __restrict__ out) {
    out[threadIdx.x] = g_seq[0][(size_t)(Tm - 1) * Dm + threadIdx.x];
}

// ---------------- launch ------------------------------------------------------
extern "C" void kernel_launch(void* const* d_in, const int* in_sizes, int n_in,
                              void* d_out, int out_size) {
    const float* x    = (const float*)d_in[0];
    const float* rn   = (const float*)d_in[1];
    const float* dtp  = (const float*)d_in[2];
    const float* rw   = (const float*)d_in[3];
    const float* rb   = (const float*)d_in[4];
    const float* Wf1  = (const float*)d_in[5];
    const float* bf1  = (const float*)d_in[6];
    const float* Wf2  = (const float*)d_in[7];
    const float* bf2  = (const float*)d_in[8];
    const float* Wta  = (const float*)d_in[9];
    const float* bta  = (const float*)d_in[10];
    const float* Wtb  = (const float*)d_in[11];
    const float* btb  = (const float*)d_in[12];

    bias_kernel<<<(Tm * Dm) / 256, 256>>>(x, rn, rw, rb);

    for (int l = 0; l < Lm; ++l) {
        dim3 grid(4 * Dm / 64, Tm / 128);
        gemm_zx<<<grid, 256>>>(Wf1, Wf2, Wta, Wtb, bf1, bf2, bta, btb, l);
        scan_kernel<<<128, 256>>>(Wf1, Wf2, Wta, Wtb, dtp, l);
    }

    copy_out_kernel<<<1, Dm>>>((float*)d_out);
}

// round 9
// speedup vs baseline: 1.3814x; 1.3814x over previous
#include <cuda_runtime.h>
#include <cuda_bf16.h>

#define Dm 1024
#define Tm 2048
#define Lm 4

typedef unsigned long long u64;

// ---------------- device scratch (allocation-free rule) ---------------------
__device__ __align__(16) float g_seq[2][Tm * Dm];            // ping-pong seq
__device__ __align__(16) float g_zx[(size_t)Tm * 4 * Dm];    // x-part + bias
__device__ __align__(16) float g_h[2][Dm];                   // h double buffer
__device__ unsigned g_bar_count;                             // monotonic / launch

// ---------------- f32x2 helpers (sm_103a packed fp32) -----------------------
__device__ __forceinline__ u64 ffma2(u64 a, u64 b, u64 c) {
    u64 d;
    asm("fma.rn.f32x2 %0, %1, %2, %3;" : "=l"(d) : "l"(a), "l"(b), "l"(c));
    return d;
}
__device__ __forceinline__ u64 fadd2(u64 a, u64 b) {
    u64 d;
    asm("add.rn.f32x2 %0, %1, %2;" : "=l"(d) : "l"(a), "l"(b));
    return d;
}
__device__ __forceinline__ u64 pack2(float x, float y) {
    u64 r;
    asm("mov.b64 %0, {%1, %2};" : "=l"(r)
        : "r"(__float_as_uint(x)), "r"(__float_as_uint(y)));
    return r;
}
__device__ __forceinline__ float hsum2(u64 v) {
    unsigned lo, hi;
    asm("mov.b64 {%0, %1}, %2;" : "=r"(lo), "=r"(hi) : "l"(v));
    return __uint_as_float(lo) + __uint_as_float(hi);
}

// ---------------- kernel 1: persistent Re bias-add + barrier reset ----------
__global__ void bias_kernel(const float* __restrict__ x, const float* __restrict__ rn,
                            const float* __restrict__ w, const float* __restrict__ b) {
    if (blockIdx.x == 0 && threadIdx.x == 0) g_bar_count = 0u;
    int i = blockIdx.x * 256 + threadIdx.x;
    int j = i & (Dm - 1);
    g_seq[0][i] = x[i] + rn[0] * w[j] + b[j];
}

// ---------------- kernel 2: Zx = seq_in @ Wx + bias (f32x2 GEMM) -------------
// C tile 128(m) x 64(n), BK = 16, 256 threads, 8x4 per thread.
__global__ __launch_bounds__(256, 2) void gemm_zx(
    const float* __restrict__ Wf1, const float* __restrict__ Wf2,
    const float* __restrict__ Wta, const float* __restrict__ Wtb,
    const float* __restrict__ bf1, const float* __restrict__ bf2,
    const float* __restrict__ bta, const float* __restrict__ btb,
    int layer)
{
    __shared__ u64   As2[8][128];      // [k-pair][m]
    __shared__ float Bsf[8][64][2];    // [k-pair][n][k parity]

    const int tid = threadIdx.x;
    const int tx = tid & 15;           // n within tile (x16)
    const int ty = tid >> 4;           // m within tile (x16)
    const int m0 = blockIdx.y * 128;
    const int n0 = blockIdx.x * 64;    // global col in [0,4096)
    const int blk = n0 >> 10;          // which weight block
    const int j0  = n0 & (Dm - 1);

    const float* Wb = (blk == 0) ? Wf1 : ((blk == 1) ? Wf2 : ((blk == 2) ? Wta : Wtb));
    const float* bb = (blk == 0) ? bf1 : ((blk == 1) ? bf2 : ((blk == 2) ? bta : btb));
    const float* Bp = Wb + (size_t)layer * 2 * Dm * Dm + j0;   // x rows 0..D-1
    const float* A  = g_seq[layer & 1];

    u64 acc[8][4];
#pragma unroll
    for (int i = 0; i < 8; i++)
#pragma unroll
        for (int j = 0; j < 4; j++) acc[i][j] = 0ull;

    for (int k0 = 0; k0 < Dm; k0 += 16) {
#pragma unroll
        for (int it = 0; it < 2; it++) {
            int i   = tid + it * 256;
            int row = i >> 2;
            int f4  = i & 3;
            float4 v = *(const float4*)(A + (size_t)(m0 + row) * Dm + k0 + f4 * 4);
            As2[f4 * 2 + 0][row] = pack2(v.x, v.y);
            As2[f4 * 2 + 1][row] = pack2(v.z, v.w);
        }
        {
            int kr = tid >> 4;
            int j4 = tid & 15;
            float4 v = *(const float4*)(Bp + (size_t)(k0 + kr) * Dm + j4 * 4);
            Bsf[kr >> 1][j4 * 4 + 0][kr & 1] = v.x;
            Bsf[kr >> 1][j4 * 4 + 1][kr & 1] = v.y;
            Bsf[kr >> 1][j4 * 4 + 2][kr & 1] = v.z;
            Bsf[kr >> 1][j4 * 4 + 3][kr & 1] = v.w;
        }
        __syncthreads();
#pragma unroll
        for (int kk = 0; kk < 8; kk++) {
            u64 a2[8], b2[4];
#pragma unroll
            for (int ii = 0; ii < 8; ii++) a2[ii] = As2[kk][ii * 16 + ty];
#pragma unroll
            for (int jj = 0; jj < 4; jj++) b2[jj] = *(const u64*)&Bsf[kk][jj * 16 + tx][0];
#pragma unroll
            for (int ii = 0; ii < 8; ii++)
#pragma unroll
                for (int jj = 0; jj < 4; jj++)
                    acc[ii][jj] = ffma2(a2[ii], b2[jj], acc[ii][jj]);
        }
        __syncthreads();
    }

    float bias[4];
#pragma unroll
    for (int jj = 0; jj < 4; jj++) bias[jj] = bb[(size_t)layer * Dm + j0 + jj * 16 + tx];
#pragma unroll
    for (int ii = 0; ii < 8; ii++) {
        size_t row = (size_t)(m0 + ii * 16 + ty);
#pragma unroll
        for (int jj = 0; jj < 4; jj++)
            g_zx[row * 4096 + n0 + jj * 16 + tx] = hsum2(acc[ii][jj]) + bias[jj];
    }
}

// ---------------- kernel 3: sequential scan ----------------------------------
// 128 CTAs x 256 threads, persistent. CTA b owns dims 8b..8b+7, warp w -> dim.
// Lane = blk*8 + chunk: blk picks gate matrix, chunk picks 128-wide k range.
// Barrier: monotonic counter, red.release arrival + ld.acquire spin (warp 0).
__global__ __launch_bounds__(256, 1) void scan_kernel(
    const float* __restrict__ Wf1, const float* __restrict__ Wf2,
    const float* __restrict__ Wta, const float* __restrict__ Wtb,
    const float* __restrict__ dt_ptr, int layer)
{
    __shared__ __align__(16) float sh[Dm];   // h staged, chunk-interleaved

    const int tid  = threadIdx.x;
    const int lane = tid & 31;
    const int w    = tid >> 5;               // warp -> dim
    const int blk  = lane >> 3;              // 0..3 gate
    const int ch   = lane & 7;               // k chunk
    const int dim  = blockIdx.x * 8 + w;
    const float dt = dt_ptr[0];
    const unsigned base = (unsigned)layer * 2047u * 128u;
    unsigned* const cnt = &g_bar_count;

    const float* Wsel = (blk == 0) ? Wf1 : ((blk == 1) ? Wf2 : ((blk == 2) ? Wta : Wtb));
    const float* Wp = Wsel + (size_t)layer * 2 * Dm * Dm
                    + (size_t)(Dm + ch * 128) * Dm + dim;

    // this lane's 128 Wh values as 64 f32x2 pairs (k pairs 2i,2i+1)
    u64 wreg[64];
#pragma unroll
    for (int i = 0; i < 64; i++)
        wreg[i] = pack2(Wp[(size_t)(2 * i) * Dm], Wp[(size_t)(2 * i + 1) * Dm]);

    float* __restrict__ outseq = g_seq[(layer + 1) & 1];
    const bool zlane = (ch == 0);
    float zx_cur = zlane ? __ldg(&g_zx[(size_t)blk * Dm + dim]) : 0.0f;

    // staging indices (fixed per thread)
    const int sc = tid & 7, sf = tid >> 3;

    for (int t = 0; t < Tm; ++t) {
        // ---- stage h_t into smem (chunk-interleaved, conflict-free) ----
        {
            float4 v;
            if (t == 0) { v.x = v.y = v.z = v.w = 0.0f; }
            else {
                v = __ldcg((const float4*)&g_h[t & 1][sc * 128 + sf * 4]);
            }
            *(float4*)&sh[sf * 32 + sc * 4] = v;
        }
        __syncthreads();

        // ---- partial dot: 128 k via 64 packed FMAs, 4 accumulator chains ----
        u64 a0 = 0ull, a1 = 0ull, a2 = 0ull, a3 = 0ull;
        const float4* sh4 = (const float4*)sh;
#pragma unroll
        for (int f = 0; f < 32; f += 2) {
            float4 h0 = sh4[f * 8 + ch];
            float4 h1 = sh4[(f + 1) * 8 + ch];
            a0 = ffma2(pack2(h0.x, h0.y), wreg[2 * f + 0], a0);
            a1 = ffma2(pack2(h0.z, h0.w), wreg[2 * f + 1], a1);
            a2 = ffma2(pack2(h1.x, h1.y), wreg[2 * f + 2], a2);
            a3 = ffma2(pack2(h1.z, h1.w), wreg[2 * f + 3], a3);
        }
        float s = hsum2(fadd2(fadd2(a0, a1), fadd2(a2, a3)));
        s += __shfl_xor_sync(0xffffffffu, s, 1);
        s += __shfl_xor_sync(0xffffffffu, s, 2);
        s += __shfl_xor_sync(0xffffffffu, s, 4);
        if (zlane) s += zx_cur;

        float z1 = __shfl_sync(0xffffffffu, s, 0);
        float z2 = __shfl_sync(0xffffffffu, s, 8);
        float za = __shfl_sync(0xffffffffu, s, 16);
        float zb = __shfl_sync(0xffffffffu, s, 24);

        float f1 = tanhf(z1);
        float f2 = tanhf(z2);
        float g  = __fdividef(1.0f, 1.0f + expf(za * dt - zb));  // sigmoid(-za*dt+zb)
        float hn = g * f1 + (1.0f - g) * f2;

        if (lane == 0) {
            g_h[(t + 1) & 1][dim] = hn;
            outseq[(size_t)t * Dm + dim] = hn;
        }

        if (t + 1 < Tm) {
            __syncthreads();                         // all warps wrote h
            if (tid == 0)
                asm volatile("red.release.gpu.global.add.u32 [%0], %1;"
                             :: "l"(cnt), "r"(1u) : "memory");
            // prefetch Zx for t+1 (DRAM latency hidden under the spin)
            float zx_next = zlane
                ? __ldg(&g_zx[(size_t)(t + 1) * 4096 + blk * Dm + dim]) : 0.0f;
            if (w == 0) {                            // warp 0 spins
                const unsigned target = base + 128u * (unsigned)(t + 1);
                unsigned v;
                do {
                    asm volatile("ld.acquire.gpu.global.u32 %0, [%1];"
                                 : "=r"(v) : "l"(cnt) : "memory");
                } while (v < target);
            }
            __syncthreads();                         // release the CTA
            zx_cur = zx_next;
        }
    }
}

// ---------------- kernel 4: emit final h -------------------------------------
__global__ void copy_out_kernel(float* __restrict__ out) {
    out[threadIdx.x] = g_seq[0][(size_t)(Tm - 1) * Dm + threadIdx.x];
}

// ---------------- launch ------------------------------------------------------
extern "C" void kernel_launch(void* const* d_in, const int* in_sizes, int n_in,
                              void* d_out, int out_size) {
    const float* x    = (const float*)d_in[0];
    const float* rn   = (const float*)d_in[1];
    const float* dtp  = (const float*)d_in[2];
    const float* rw   = (const float*)d_in[3];
    const float* rb   = (const float*)d_in[4];
    const float* Wf1  = (const float*)d_in[5];
    const float* bf1  = (const float*)d_in[6];
    const float* Wf2  = (const float*)d_in[7];
    const float* bf2  = (const float*)d_in[8];
    const float* Wta  = (const float*)d_in[9];
    const float* bta  = (const float*)d_in[10];
    const float* Wtb  = (const float*)d_in[11];
    const float* btb  = (const float*)d_in[12];

    bias_kernel<<<(Tm * Dm) / 256, 256>>>(x, rn, rw, rb);

    for (int l = 0; l < Lm; ++l) {
        dim3 grid(4 * Dm / 64, Tm / 128);
        gemm_zx<<<grid, 256>>>(Wf1, Wf2, Wta, Wtb, bf1, bf2, bta, btb, l);
        scan_kernel<<<128, 256>>>(Wf1, Wf2, Wta, Wtb, dtp, l);
    }

    copy_out_kernel<<<1, Dm>>>((float*)d_out);
}